// round 5
// baseline (speedup 1.0000x reference)
#include <cuda_runtime.h>
#include <cuda_bf16.h>

// Problem shape (fixed by reference setup_inputs)
#define BB 16
#define CC 20
#define HHH 256
#define WWW 256
constexpr int NCH = BB * CC;                       // 320
constexpr int HWC = HHH * WWW;                     // 65536
constexpr long long NTOT = (long long)NCH * HWC;   // 20971520
constexpr int BLOCKS_PER_CH = 8;
constexpr int THREADS = 256;
constexpr int NBLOCKS = NCH * BLOCKS_PER_CH;       // 2560
constexpr int CHUNK = HWC / BLOCKS_PER_CH;         // 8192 elems
constexpr int ITERS = CHUNK / (4 * THREADS);       // 8 float4 per thread

// Per-block partials: [focal, mse, l1, Sp, Spy, Spx, Spr2, mass, Sty, Stx]
// Overwritten by every block each launch -> no zeroing needed, deterministic
// across graph replays.
__device__ float g_part[NBLOCKS * 10];
__device__ unsigned int g_count;   // zero-init once; finalizing block resets it.

__global__ __launch_bounds__(THREADS) void fused_kernel(
    const float4* __restrict__ pred, const float4* __restrict__ targ,
    float* __restrict__ out, int out_size)
{
    const int blk = blockIdx.x;
    const int ch  = blk >> 3;          // / BLOCKS_PER_CH
    const int sub = blk & 7;
    const int base4 = (ch * HWC + sub * CHUNK) >> 2;

    float focal = 0.f, mse = 0.f, l1 = 0.f;
    float Sp = 0.f, Spy = 0.f, Spx = 0.f, Spr2 = 0.f;
    float mass = 0.f, Sty = 0.f, Stx = 0.f;

#pragma unroll
    for (int it = 0; it < ITERS; ++it) {
        const int idx4 = base4 + it * THREADS + threadIdx.x;
        const float4 pr = __ldg(&pred[idx4]);   // ld.global.nc.v4 path
        const float4 tg = __ldg(&targ[idx4]);

        const int hw = (idx4 << 2) & (HWC - 1);
        const float y  = (float)(hw >> 8);
        const float x0 = (float)(hw & 255);
        const float yy = y * y;

#define LANE(PV, TV, XO)                                                    \
        {                                                                   \
            float pv = (PV), tv = (TV);                                     \
            float x  = x0 + (XO);                                           \
            float p  = __fdividef(1.0f, 1.0f + __expf(-pv));                \
            /* pt = t ? p : 1-p  (t is exactly 0 or 1) */                   \
            float pt = fmaf(2.0f * p - 1.0f, tv, 1.0f - p);                 \
            float at = 0.75f - 0.5f * tv;                                   \
            float omp = 1.0f - pt;                                          \
            focal = fmaf(at * omp * omp, -__logf(pt + 1e-8f), focal);       \
            float d = pv - tv;                                              \
            mse = fmaf(d, d, mse);                                          \
            l1 += fabsf(pv);                                                \
            Sp  += p;                                                       \
            Spy = fmaf(p, y, Spy);                                          \
            Spx = fmaf(p, x, Spx);                                          \
            Spr2 = fmaf(p, fmaf(x, x, yy), Spr2);                           \
            mass += tv;                                                     \
            Sty = fmaf(tv, y, Sty);                                         \
            Stx = fmaf(tv, x, Stx);                                         \
        }

        LANE(pr.x, tg.x, 0.0f)
        LANE(pr.y, tg.y, 1.0f)
        LANE(pr.z, tg.z, 2.0f)
        LANE(pr.w, tg.w, 3.0f)
#undef LANE
    }

    // ---- block reduction of 10 values ----
    float vals[10] = {focal, mse, l1, Sp, Spy, Spx, Spr2, mass, Sty, Stx};
#pragma unroll
    for (int v = 0; v < 10; v++) {
#pragma unroll
        for (int o = 16; o > 0; o >>= 1)
            vals[v] += __shfl_xor_sync(0xffffffffu, vals[v], o);
    }

    __shared__ float sred[THREADS / 32][10];
    const int warp = threadIdx.x >> 5;
    const int lane = threadIdx.x & 31;
    if (lane == 0) {
#pragma unroll
        for (int v = 0; v < 10; v++) sred[warp][v] = vals[v];
    }
    __syncthreads();

    if (threadIdx.x < 10) {
        float s = 0.f;
#pragma unroll
        for (int w = 0; w < THREADS / 32; w++) s += sred[w][threadIdx.x];
        g_part[blk * 10 + threadIdx.x] = s;   // private slot, no atomics
        __threadfence();                       // release: only these 10 threads
    }
    __syncthreads();

    // ---- last-block-done finalize (fused; no extra launch) ----
    __shared__ bool s_last;
    if (threadIdx.x == 0) {
        const unsigned int prev = atomicAdd(&g_count, 1u);
        s_last = (prev == (unsigned int)(NBLOCKS - 1));
    }
    __syncthreads();
    if (!s_last) return;
    if (threadIdx.x == 0) __threadfence();   // acquire side
    __syncthreads();

    const int tid = threadIdx.x;
    float conc = 0.f, nv = 0.f, fo = 0.f, ms = 0.f, la = 0.f;

    // 320 channels over 256 threads: tid handles ch=tid and (tid<64) ch=tid+256
#pragma unroll
    for (int rep = 0; rep < 2; rep++) {
        const int c = tid + rep * THREADS;
        if (c < NCH) {
            float s[7] = {0, 0, 0, 0, 0, 0, 0};
#pragma unroll
            for (int sb = 0; sb < BLOCKS_PER_CH; sb++) {
                const float* a = &g_part[(c * BLOCKS_PER_CH + sb) * 10];
                fo += __ldcg(&a[0]); ms += __ldcg(&a[1]); la += __ldcg(&a[2]);
#pragma unroll
                for (int v = 0; v < 7; v++) s[v] += __ldcg(&a[3 + v]);
            }
            const float SSp = s[0], SSpy = s[1], SSpx = s[2], SSpr2 = s[3];
            const float smass = s[4], SSty = s[5], SStx = s[6];
            const bool valid = smass > 0.0f;
            const float safe = valid ? smass : 1.0f;
            const float cy = SSty / safe;
            const float cx = SStx / safe;
            const float ps = (SSpr2 - 2.0f * (cy * SSpy + cx * SSpx)
                              + (cy * cy + cx * cx) * SSp) * (1.0f / (float)HWC);
            if (valid) { conc += ps; nv += 1.0f; }
        }
    }

    float red[5] = {conc, nv, fo, ms, la};
#pragma unroll
    for (int v = 0; v < 5; v++) {
#pragma unroll
        for (int o = 16; o > 0; o >>= 1)
            red[v] += __shfl_xor_sync(0xffffffffu, red[v], o);
    }
    __shared__ float sr[THREADS / 32][5];
    if (lane == 0) {
#pragma unroll
        for (int v = 0; v < 5; v++) sr[warp][v] = red[v];
    }
    __syncthreads();

    if (tid == 0) {
        float tot[5] = {0, 0, 0, 0, 0};
#pragma unroll
        for (int w = 0; w < THREADS / 32; w++)
#pragma unroll
            for (int v = 0; v < 5; v++) tot[v] += sr[w][v];

        const float inv = 1.0f / (float)NTOT;
        const float focal_m = tot[2] * inv;
        const float sparsity = tot[3] * inv + tot[4] * inv;  // mse + 1.0*L1
        const float concentration = (tot[1] > 0.f) ? (tot[0] / tot[1]) : 0.0f;
        const float total = 1.0f * focal_m + 0.8f * sparsity + 1.5f * concentration;

        out[0] = total;
        if (out_size > 1) out[1] = focal_m;
        if (out_size > 2) out[2] = sparsity;
        if (out_size > 3) out[3] = concentration;

        g_count = 0;          // reset for next graph replay (deterministic)
        __threadfence();
    }
}

extern "C" void kernel_launch(void* const* d_in, const int* in_sizes, int n_in,
                              void* d_out, int out_size) {
    const float4* pred = (const float4*)d_in[0];
    const float4* targ = (const float4*)d_in[1];
    float* out = (float*)d_out;

    fused_kernel<<<NBLOCKS, THREADS>>>(pred, targ, out, out_size);
}

// round 6
// speedup vs baseline: 1.5474x; 1.5474x over previous
#include <cuda_runtime.h>
#include <cuda_bf16.h>

// Problem shape (fixed by reference setup_inputs)
#define BB 16
#define CC 20
#define HHH 256
#define WWW 256
constexpr int NCH = BB * CC;                       // 320
constexpr int HWC = HHH * WWW;                     // 65536
constexpr long long NTOT = (long long)NCH * HWC;   // 20971520
constexpr int BLOCKS_PER_CH = 4;
constexpr int THREADS = 256;
constexpr int NBLOCKS = NCH * BLOCKS_PER_CH;       // 1280
constexpr int CHUNK = HWC / BLOCKS_PER_CH;         // 16384 elems
constexpr int ITERS = CHUNK / (4 * THREADS);       // 16 float4 per thread

// Transposed per-block partials: g_part[v * NBLOCKS + blk], v in
// [focal, mse, l1, Sp, Spy, Spx, Spr2, mass, Sty, Stx].
// Every block overwrites its slot each launch -> no zeroing, deterministic
// across graph replays. Kernel boundary orders pass -> final (no fences).
__device__ float g_part[10 * NBLOCKS];

__global__ __launch_bounds__(THREADS) void pass_kernel(
    const float4* __restrict__ pred, const float4* __restrict__ targ)
{
    const int blk = blockIdx.x;
    const int ch  = blk >> 2;
    const int sub = blk & 3;
    const int base4 = (ch * HWC + sub * CHUNK) >> 2;

    float focal = 0.f, mse = 0.f, l1 = 0.f;
    float Sp = 0.f, Spy = 0.f, Spx = 0.f, Spr2 = 0.f;
    float mass = 0.f, Sty = 0.f, Stx = 0.f;

#pragma unroll
    for (int it = 0; it < ITERS; ++it) {
        const int idx4 = base4 + it * THREADS + threadIdx.x;
        const float4 pr = pred[idx4];
        const float4 tg = targ[idx4];

        const int hw = (idx4 << 2) & (HWC - 1);
        const float y  = (float)(hw >> 8);
        const float x0 = (float)(hw & 255);
        const float yy = y * y;

#define LANE(PV, TV, XO)                                                    \
        {                                                                   \
            float pv = (PV), tv = (TV);                                     \
            float x  = x0 + (XO);                                           \
            float p  = __fdividef(1.0f, 1.0f + __expf(-pv));                \
            /* pt = t ? p : 1-p  (t is exactly 0 or 1) */                   \
            float pt = fmaf(2.0f * p - 1.0f, tv, 1.0f - p);                 \
            float at = 0.75f - 0.5f * tv;                                   \
            float omp = 1.0f - pt;                                          \
            focal = fmaf(at * omp * omp, -__logf(pt + 1e-8f), focal);       \
            float d = pv - tv;                                              \
            mse = fmaf(d, d, mse);                                          \
            l1 += fabsf(pv);                                                \
            Sp  += p;                                                       \
            Spy = fmaf(p, y, Spy);                                          \
            Spx = fmaf(p, x, Spx);                                          \
            Spr2 = fmaf(p, fmaf(x, x, yy), Spr2);                           \
            mass += tv;                                                     \
            Sty = fmaf(tv, y, Sty);                                         \
            Stx = fmaf(tv, x, Stx);                                         \
        }

        LANE(pr.x, tg.x, 0.0f)
        LANE(pr.y, tg.y, 1.0f)
        LANE(pr.z, tg.z, 2.0f)
        LANE(pr.w, tg.w, 3.0f)
#undef LANE
    }

    // ---- block reduction of 10 values ----
    float vals[10] = {focal, mse, l1, Sp, Spy, Spx, Spr2, mass, Sty, Stx};
#pragma unroll
    for (int v = 0; v < 10; v++) {
#pragma unroll
        for (int o = 16; o > 0; o >>= 1)
            vals[v] += __shfl_xor_sync(0xffffffffu, vals[v], o);
    }

    __shared__ float sred[THREADS / 32][10];
    const int warp = threadIdx.x >> 5;
    const int lane = threadIdx.x & 31;
    if (lane == 0) {
#pragma unroll
        for (int v = 0; v < 10; v++) sred[warp][v] = vals[v];
    }
    __syncthreads();

    if (threadIdx.x < 10) {
        float s = 0.f;
#pragma unroll
        for (int w = 0; w < THREADS / 32; w++) s += sred[w][threadIdx.x];
        g_part[threadIdx.x * NBLOCKS + blk] = s;   // transposed, private slot
    }
}

__global__ __launch_bounds__(NCH) void final_kernel(
    float* __restrict__ out, int out_size)
{
    const int tid = threadIdx.x;   // 320 threads, one channel each

    // Channel-sum over 4 consecutive block slots per value: coalesced reads.
    float s[10];
#pragma unroll
    for (int v = 0; v < 10; v++) {
        const float4 q = *(const float4*)&g_part[v * NBLOCKS + tid * BLOCKS_PER_CH];
        s[v] = (q.x + q.y) + (q.z + q.w);
    }

    float conc = 0.f, nv = 0.f;
    {
        const float Sp = s[3], Spy = s[4], Spx = s[5], Spr2 = s[6];
        const float mass = s[7], Sty = s[8], Stx = s[9];
        const bool valid = mass > 0.0f;
        const float safe = valid ? mass : 1.0f;
        const float cy = Sty / safe;
        const float cx = Stx / safe;
        const float ps = (Spr2 - 2.0f * (cy * Spy + cx * Spx)
                          + (cy * cy + cx * cx) * Sp) * (1.0f / (float)HWC);
        if (valid) { conc = ps; nv = 1.0f; }
    }

    float red[5] = {conc, nv, s[0], s[1], s[2]};
#pragma unroll
    for (int v = 0; v < 5; v++) {
#pragma unroll
        for (int o = 16; o > 0; o >>= 1)
            red[v] += __shfl_xor_sync(0xffffffffu, red[v], o);
    }
    __shared__ float sr[NCH / 32][5];
    const int warp = tid >> 5, lane = tid & 31;
    if (lane == 0) {
#pragma unroll
        for (int v = 0; v < 5; v++) sr[warp][v] = red[v];
    }
    __syncthreads();

    if (tid == 0) {
        float tot[5] = {0, 0, 0, 0, 0};
#pragma unroll
        for (int w = 0; w < NCH / 32; w++)
#pragma unroll
            for (int v = 0; v < 5; v++) tot[v] += sr[w][v];

        const float inv = 1.0f / (float)NTOT;
        const float focal_m = tot[2] * inv;
        const float sparsity = tot[3] * inv + tot[4] * inv;  // mse + 1.0*L1
        const float concentration = (tot[1] > 0.f) ? (tot[0] / tot[1]) : 0.0f;
        const float total = 1.0f * focal_m + 0.8f * sparsity + 1.5f * concentration;

        out[0] = total;
        if (out_size > 1) out[1] = focal_m;
        if (out_size > 2) out[2] = sparsity;
        if (out_size > 3) out[3] = concentration;
    }
}

extern "C" void kernel_launch(void* const* d_in, const int* in_sizes, int n_in,
                              void* d_out, int out_size) {
    const float4* pred = (const float4*)d_in[0];
    const float4* targ = (const float4*)d_in[1];
    float* out = (float*)d_out;

    pass_kernel<<<NBLOCKS, THREADS>>>(pred, targ);
    final_kernel<<<1, NCH>>>(out, out_size);
}